// round 4
// baseline (speedup 1.0000x reference)
#include <cuda_runtime.h>
#include <cuda_bf16.h>

#define D_IN   128
#define D_OUT  64
#define MAXN   50000

typedef unsigned long long u64;

__device__ float g_T[2][MAXN * D_OUT];
__device__ float g_ACC[2][MAXN * D_OUT];

__device__ __forceinline__ void fma2(u64& d, u64 a, u64 b) {
    asm("fma.rn.f32x2 %0, %1, %2, %3;" : "=l"(d) : "l"(a), "l"(b), "l"(d));
}
__device__ __forceinline__ u64 pack_dup(float x) {
    u64 r; asm("mov.b64 %0, {%1, %1};" : "=l"(r) : "f"(x)); return r;
}
__device__ __forceinline__ void unpack2(u64 v, float& lo, float& hi) {
    asm("mov.b64 {%0, %1}, %2;" : "=f"(lo), "=f"(hi) : "l"(v));
}

// ---------------------------------------------------------------------------
// Kernel A: fused dual-projection GEMM, both relations (grid.y = rel).
// [128 x 128] tile of X[N,128] @ Wc^T; Wc rows 0..63 = Wrel (-> g_T),
// rows 64..127 = Wroot (+brel -> g_ACC).
// Thread tile: 8 rows x (4 cols in [0,64) + 4 cols in [64,128)).
// Packed f32x2 FMA; Xs reads vectorized over k (LDS.64 = 2 k-steps);
// Ws reads as 2 bank-spread LDS.128 reinterpreted as u64 pairs.
// ---------------------------------------------------------------------------
__global__ __launch_bounds__(256, 2) void transform_kernel(
    const float* __restrict__ X0, const float* __restrict__ X1,
    const float* __restrict__ Wrel0, const float* __restrict__ brel0,
    const float* __restrict__ Wroot0,
    const float* __restrict__ Wrel1, const float* __restrict__ brel1,
    const float* __restrict__ Wroot1,
    int N)
{
    __shared__ float Ws[32][128];   // Ws[k][c], c: 0..63 rel, 64..127 root
    __shared__ float Xs[128][36];   // Xs[r][k], stride 36 (16B-aligned rows)
    __shared__ float bs[64];

    const int rel = blockIdx.y;
    const float* __restrict__ X     = rel ? X1 : X0;
    const float* __restrict__ Wrel  = rel ? Wrel1 : Wrel0;
    const float* __restrict__ brel  = rel ? brel1 : brel0;
    const float* __restrict__ Wroot = rel ? Wroot1 : Wroot0;

    const int tid = threadIdx.x;
    const int tx  = tid & 15;   // col groups: [tx*4, tx*4+4) and [64+tx*4, ...)
    const int ty  = tid >> 4;   // rows ty*8 .. ty*8+7
    const int row0 = blockIdx.x * 128;

    if (tid < 64) bs[tid] = brel[tid];

    // acc[i][0..1] -> cols tx*4..+3 (rel part); acc[i][2..3] -> cols 64+tx*4..+3
    u64 acc[8][4];
#pragma unroll
    for (int i = 0; i < 8; i++)
#pragma unroll
        for (int j = 0; j < 4; j++) acc[i][j] = 0ull;

    for (int kc = 0; kc < 4; kc++) {
        const int kb = kc * 32;

        // Ws[k][c]: 4096 floats via float4-over-k, c fastest across lanes.
#pragma unroll
        for (int i = 0; i < 4; i++) {
            int idx = tid + i * 256;
            int c   = idx & 127;
            int kq  = idx >> 7;
            const float* wsrc = (c < 64) ? (Wrel + c * D_IN)
                                         : (Wroot + (c - 64) * D_IN);
            float4 w = *(const float4*)(wsrc + kb + kq * 4);
            Ws[kq * 4 + 0][c] = w.x;
            Ws[kq * 4 + 1][c] = w.y;
            Ws[kq * 4 + 2][c] = w.z;
            Ws[kq * 4 + 3][c] = w.w;
        }

        // Xs[r][k]: coalesced float4 reads, aligned STS.128 (row stride 144B).
#pragma unroll
        for (int i = 0; i < 4; i++) {
            int idx = tid + i * 256;
            int r   = idx >> 3;
            int kq  = idx & 7;
            int grow = row0 + r;
            float4 v = make_float4(0.f, 0.f, 0.f, 0.f);
            if (grow < N) v = *(const float4*)(X + (long)grow * D_IN + kb + kq * 4);
            *(float4*)&Xs[r][kq * 4] = v;
        }

        __syncthreads();

#pragma unroll
        for (int k2 = 0; k2 < 16; k2++) {
            // 2 k-steps per iteration; vectorized Xs reads.
            float2 la[8];
#pragma unroll
            for (int i = 0; i < 8; i++)
                la[i] = *(const float2*)&Xs[ty * 8 + i][k2 * 2];

#pragma unroll
            for (int kk = 0; kk < 2; kk++) {
                const float* wrow = Ws[k2 * 2 + kk];
                ulonglong2 wa = *(const ulonglong2*)&wrow[tx * 4];
                ulonglong2 wb = *(const ulonglong2*)&wrow[64 + tx * 4];
                u64 b2[4] = { wa.x, wa.y, wb.x, wb.y };
#pragma unroll
                for (int i = 0; i < 8; i++) {
                    u64 ad = pack_dup(kk ? la[i].y : la[i].x);
                    fma2(acc[i][0], ad, b2[0]);
                    fma2(acc[i][1], ad, b2[1]);
                    fma2(acc[i][2], ad, b2[2]);
                    fma2(acc[i][3], ad, b2[3]);
                }
            }
        }
        __syncthreads();
    }

    // Epilogue: group 0 -> g_T, group 1 -> g_ACC (+brel). No divergence.
    float* Tout = g_T[rel];
    float* Aout = g_ACC[rel];
    const int c = tx * 4;
#pragma unroll
    for (int i = 0; i < 8; i++) {
        int row = row0 + ty * 8 + i;
        if (row >= N) break;
        float t0, t1, t2, t3, a0, a1, a2, a3;
        unpack2(acc[i][0], t0, t1);
        unpack2(acc[i][1], t2, t3);
        unpack2(acc[i][2], a0, a1);
        unpack2(acc[i][3], a2, a3);
        *(float4*)(Tout + (long)row * D_OUT + c) = make_float4(t0, t1, t2, t3);
        *(float4*)(Aout + (long)row * D_OUT + c) =
            make_float4(a0 + bs[c + 0], a1 + bs[c + 1], a2 + bs[c + 2], a3 + bs[c + 3]);
    }
}

// ---------------------------------------------------------------------------
// Kernel B: edge scatter-add in projected 64-dim space, both relations
// (grid.y = rel). 16 lanes per edge-slot; each slot handles 4 edges (MLP=4).
// ---------------------------------------------------------------------------
__global__ __launch_bounds__(256) void scatter_kernel(
    const int* __restrict__ edges0, const int* __restrict__ edges1, int E)
{
    const int rel = blockIdx.y;
    const int* __restrict__ edges = rel ? edges1 : edges0;
    const float* __restrict__ T = g_T[rel];
    float* __restrict__ A = g_ACC[rel];

    int idx  = blockIdx.x * blockDim.x + threadIdx.x;
    int slot = idx >> 4;
    int lane = idx & 15;
    int e0   = slot * 4;
    if (e0 >= E) return;

    if (e0 + 4 <= E) {
        int4 s4 = *(const int4*)(edges + e0);
        int4 d4 = *(const int4*)(edges + E + e0);

        // 4 independent gathers (MLP=4), then 4 reductions.
        float4 v0 = *(const float4*)(T + (long)s4.x * D_OUT + lane * 4);
        float4 v1 = *(const float4*)(T + (long)s4.y * D_OUT + lane * 4);
        float4 v2 = *(const float4*)(T + (long)s4.z * D_OUT + lane * 4);
        float4 v3 = *(const float4*)(T + (long)s4.w * D_OUT + lane * 4);

        float* p0 = A + (long)d4.x * D_OUT + lane * 4;
        float* p1 = A + (long)d4.y * D_OUT + lane * 4;
        float* p2 = A + (long)d4.z * D_OUT + lane * 4;
        float* p3 = A + (long)d4.w * D_OUT + lane * 4;
        asm volatile("red.global.add.v4.f32 [%0], {%1,%2,%3,%4};"
                     :: "l"(p0), "f"(v0.x), "f"(v0.y), "f"(v0.z), "f"(v0.w) : "memory");
        asm volatile("red.global.add.v4.f32 [%0], {%1,%2,%3,%4};"
                     :: "l"(p1), "f"(v1.x), "f"(v1.y), "f"(v1.z), "f"(v1.w) : "memory");
        asm volatile("red.global.add.v4.f32 [%0], {%1,%2,%3,%4};"
                     :: "l"(p2), "f"(v2.x), "f"(v2.y), "f"(v2.z), "f"(v2.w) : "memory");
        asm volatile("red.global.add.v4.f32 [%0], {%1,%2,%3,%4};"
                     :: "l"(p3), "f"(v3.x), "f"(v3.y), "f"(v3.z), "f"(v3.w) : "memory");
    } else {
        for (int e = e0; e < E; e++) {
            int src = edges[e];
            int dst = edges[E + e];
            float4 v = *(const float4*)(T + (long)src * D_OUT + lane * 4);
            float* p = A + (long)dst * D_OUT + lane * 4;
            asm volatile("red.global.add.v4.f32 [%0], {%1,%2,%3,%4};"
                         :: "l"(p), "f"(v.x), "f"(v.y), "f"(v.z), "f"(v.w) : "memory");
        }
    }
}

// ---------------------------------------------------------------------------
// Kernel C: fused relu + concat-dot with Wfc + bias. 16 threads/node.
// ---------------------------------------------------------------------------
__global__ __launch_bounds__(256) void output_kernel(
    const float* __restrict__ Wfc, const float* __restrict__ bfc,
    float* __restrict__ out, int N)
{
    __shared__ float wf[128];
    int tid = threadIdx.x;
    if (tid < 128) wf[tid] = Wfc[tid];
    __syncthreads();

    int idx  = blockIdx.x * blockDim.x + tid;
    int node = idx >> 4;
    int lane = idx & 15;
    if (node >= N) return;

    float4 a = *(const float4*)(g_ACC[0] + (long)node * D_OUT + lane * 4);
    float4 b = *(const float4*)(g_ACC[1] + (long)node * D_OUT + lane * 4);

    int c = lane * 4;
    float s = 0.0f;
    s += fmaxf(a.x, 0.f) * wf[c + 0];
    s += fmaxf(a.y, 0.f) * wf[c + 1];
    s += fmaxf(a.z, 0.f) * wf[c + 2];
    s += fmaxf(a.w, 0.f) * wf[c + 3];
    s += fmaxf(b.x, 0.f) * wf[64 + c + 0];
    s += fmaxf(b.y, 0.f) * wf[64 + c + 1];
    s += fmaxf(b.z, 0.f) * wf[64 + c + 2];
    s += fmaxf(b.w, 0.f) * wf[64 + c + 3];

#pragma unroll
    for (int off = 8; off > 0; off >>= 1)
        s += __shfl_down_sync(0xFFFFFFFFu, s, off, 16);

    if (lane == 0) out[node] = s + bfc[0];
}

// ---------------------------------------------------------------------------
extern "C" void kernel_launch(void* const* d_in, const int* in_sizes, int n_in,
                              void* d_out, int out_size)
{
    const float* x0     = (const float*)d_in[0];
    const float* x1     = (const float*)d_in[1];
    const int*   e0     = (const int*)d_in[2];
    const int*   e1     = (const int*)d_in[3];
    const float* Wrel0  = (const float*)d_in[4];
    const float* brel0  = (const float*)d_in[5];
    const float* Wroot0 = (const float*)d_in[6];
    const float* Wrel1  = (const float*)d_in[7];
    const float* brel1  = (const float*)d_in[8];
    const float* Wroot1 = (const float*)d_in[9];
    const float* Wfc    = (const float*)d_in[10];
    const float* bfc    = (const float*)d_in[11];
    float* out = (float*)d_out;

    const int N = in_sizes[0] / D_IN;     // 50000
    const int E = in_sizes[2] / 2;        // 600000

    dim3 tgrid((N + 127) / 128, 2);
    const int slots = (E + 3) / 4;
    dim3 sgrid((slots * 16 + 255) / 256, 2);
    const int oblocks = (N * 16 + 255) / 256;

    transform_kernel<<<tgrid, 256>>>(x0, x1, Wrel0, brel0, Wroot0,
                                     Wrel1, brel1, Wroot1, N);
    scatter_kernel<<<sgrid, 256>>>(e0, e1, E);
    output_kernel<<<oblocks, 256>>>(Wfc, bfc, out, N);
}